// round 14
// baseline (speedup 1.0000x reference)
#include <cuda_runtime.h>
#include <cuda_bf16.h>
#include <math.h>
#include <stdint.h>

#define Bc   2
#define Cc   256
#define DMc  512
#define Hc   8
#define Dc   64
#define BHc  16
#define ROWS 4096   // B*H*C

typedef unsigned long long ULL;

// ---------------- f32x2 packed helpers ----------------
__device__ __forceinline__ void fma2(ULL& d, ULL a, ULL b) {
    asm("fma.rn.f32x2 %0, %1, %2, %0;" : "+l"(d) : "l"(a), "l"(b));
}
__device__ __forceinline__ ULL fma2n(ULL a, ULL b, ULL c) {
    ULL d; asm("fma.rn.f32x2 %0, %1, %2, %3;" : "=l"(d) : "l"(a), "l"(b), "l"(c));
    return d;
}
__device__ __forceinline__ ULL mul2(ULL a, ULL b) {
    ULL d; asm("mul.rn.f32x2 %0, %1, %2;" : "=l"(d) : "l"(a), "l"(b));
    return d;
}
__device__ __forceinline__ ULL add2(ULL a, ULL b) {
    ULL d; asm("add.rn.f32x2 %0, %1, %2;" : "=l"(d) : "l"(a), "l"(b));
    return d;
}
__device__ __forceinline__ ULL dup2(float x) {
    ULL d; asm("mov.b64 %0, {%1, %1};" : "=l"(d) : "f"(x)); return d;
}
__device__ __forceinline__ ULL pack2(float x, float y) {
    ULL d; asm("mov.b64 %0, {%1, %2};" : "=l"(d) : "f"(x), "f"(y)); return d;
}
__device__ __forceinline__ void unpack2(ULL v, float& x, float& y) {
    asm("mov.b64 {%0, %1}, %2;" : "=f"(x), "=f"(y) : "l"(v));
}

// ---------------- device scratch ----------------
__device__ float g_q [ROWS * Dc];
__device__ float g_k [ROWS * Dc];
__device__ float g_v [ROWS * Dc];
__device__ float g_qp[ROWS * Dc];
__device__ float g_ctx[Bc * Cc * DMc];

// =====================================================================
// Projection GEMM body: tile 32m x 64n @ 128 threads, thread tile 2m x 8n,
// double-buffered smem.  out[m,e] = sum_d A[m,d]*W[e,d] + bias[e] (K=512)
// =====================================================================
template<bool SCATTER>
__device__ __forceinline__ void proj_body(
    const float* __restrict__ A, const float* __restrict__ W,
    const float* __restrict__ bias, float* __restrict__ out,
    int m0, int n0)
{
    __shared__ float Xs[2][16][36];
    __shared__ float Wsh[2][16][68];
    int t  = threadIdx.x;
    int tx = t & 7, ty = t >> 3;         // 8 x 16 thread grid
    int rx = t & 31, kx = (t >> 5) * 4;  // X loader
    int rw = t & 63, kw = (t >> 6) * 8;  // W loader
    const float* arow = A + (size_t)(m0 + rx) * 512 + kx;
    const float* wrow = W + (size_t)(n0 + rw) * 512 + kw;

    ULL acc[2][4];
#pragma unroll
    for (int mm = 0; mm < 2; mm++)
#pragma unroll
        for (int q = 0; q < 4; q++) acc[mm][q] = 0ULL;

    {
        float4 xv  = *(const float4*)arow;
        float4 wv0 = *(const float4*)wrow;
        float4 wv1 = *(const float4*)(wrow + 4);
        Xs[0][kx + 0][rx] = xv.x; Xs[0][kx + 1][rx] = xv.y;
        Xs[0][kx + 2][rx] = xv.z; Xs[0][kx + 3][rx] = xv.w;
        Wsh[0][kw + 0][rw] = wv0.x; Wsh[0][kw + 1][rw] = wv0.y;
        Wsh[0][kw + 2][rw] = wv0.z; Wsh[0][kw + 3][rw] = wv0.w;
        Wsh[0][kw + 4][rw] = wv1.x; Wsh[0][kw + 5][rw] = wv1.y;
        Wsh[0][kw + 6][rw] = wv1.z; Wsh[0][kw + 7][rw] = wv1.w;
    }
    __syncthreads();

    for (int kc = 0; kc < 512; kc += 16) {
        int cur = (kc >> 4) & 1;
        bool more = (kc + 16 < 512);
        float4 xv, wv0, wv1;
        if (more) {
            xv  = *(const float4*)(arow + kc + 16);
            wv0 = *(const float4*)(wrow + kc + 16);
            wv1 = *(const float4*)(wrow + kc + 16 + 4);
        }
#pragma unroll
        for (int kk = 0; kk < 16; kk++) {
            float2 av = *(const float2*)&Xs[cur][kk][ty * 2];
            ulonglong2 wa = *(const ulonglong2*)&Wsh[cur][kk][tx * 8];
            ulonglong2 wb = *(const ulonglong2*)&Wsh[cur][kk][tx * 8 + 4];
            ULL a0 = dup2(av.x), a1 = dup2(av.y);
            fma2(acc[0][0], a0, wa.x);
            fma2(acc[0][1], a0, wa.y);
            fma2(acc[0][2], a0, wb.x);
            fma2(acc[0][3], a0, wb.y);
            fma2(acc[1][0], a1, wa.x);
            fma2(acc[1][1], a1, wa.y);
            fma2(acc[1][2], a1, wb.x);
            fma2(acc[1][3], a1, wb.y);
        }
        if (more) {
            int nxt = cur ^ 1;
            Xs[nxt][kx + 0][rx] = xv.x; Xs[nxt][kx + 1][rx] = xv.y;
            Xs[nxt][kx + 2][rx] = xv.z; Xs[nxt][kx + 3][rx] = xv.w;
            Wsh[nxt][kw + 0][rw] = wv0.x; Wsh[nxt][kw + 1][rw] = wv0.y;
            Wsh[nxt][kw + 2][rw] = wv0.z; Wsh[nxt][kw + 3][rw] = wv0.w;
            Wsh[nxt][kw + 4][rw] = wv1.x; Wsh[nxt][kw + 5][rw] = wv1.y;
            Wsh[nxt][kw + 6][rw] = wv1.z; Wsh[nxt][kw + 7][rw] = wv1.w;
            __syncthreads();
        }
    }

    int nb = n0 + tx * 8;
    float bb[8];
#pragma unroll
    for (int c = 0; c < 8; c++) bb[c] = bias[nb + c];
#pragma unroll
    for (int mm = 0; mm < 2; mm++) {
        int m = m0 + ty * 2 + mm;
        float f[8];
        unpack2(acc[mm][0], f[0], f[1]);
        unpack2(acc[mm][1], f[2], f[3]);
        unpack2(acc[mm][2], f[4], f[5]);
        unpack2(acc[mm][3], f[6], f[7]);
#pragma unroll
        for (int c = 0; c < 8; c++) f[c] += bb[c];
        float* dst;
        if (SCATTER) {
            int b = m >> 8, cc = m & 255;
            int h = nb >> 6, d0 = nb & 63;
            dst = out + ((size_t)((b * 8 + h) * 256 + cc)) * 64 + d0;
        } else {
            dst = out + (size_t)m * 512 + nb;
        }
        *(float4*)dst       = make_float4(f[0], f[1], f[2], f[3]);
        *(float4*)(dst + 4) = make_float4(f[4], f[5], f[6], f[7]);
    }
}

__global__ __launch_bounds__(128) void qkv_kernel(
    const float* __restrict__ x,
    const float* __restrict__ Wq, const float* __restrict__ bq,
    const float* __restrict__ Wk, const float* __restrict__ bk,
    const float* __restrict__ Wv, const float* __restrict__ bv)
{
    int z = blockIdx.z;
    const float* W = (z == 0) ? Wq : (z == 1) ? Wk : Wv;
    const float* b = (z == 0) ? bq : (z == 1) ? bk : bv;
    float* out     = (z == 0) ? g_q : (z == 1) ? g_k : g_v;
    proj_body<true>(x, W, b, out, blockIdx.y * 32, blockIdx.x * 64);
}

__global__ __launch_bounds__(128) void outproj_kernel(
    const float* __restrict__ Wo, const float* __restrict__ bo,
    float* __restrict__ out)
{
    proj_body<false>(g_ctx, Wo, bo, out, blockIdx.y * 32, blockIdx.x * 64);
}

// =====================================================================
// q_p:  g_qp[r][e] = sum_d g_q[r][d] * w1[e][d]
// =====================================================================
__global__ __launch_bounds__(256) void qp_kernel(const float* __restrict__ w1)
{
    __shared__ float w1T[64][68];
    __shared__ float qrow[4][64];
    int t = threadIdx.x;
    int r0 = blockIdx.x * 8;

#pragma unroll
    for (int it = 0; it < 4; it++) {
        int task = t + it * 256;
        int d4 = task & 15;
        int e  = (task >> 4) & 63;
        float4 v = *(const float4*)(w1 + (size_t)e * 192 + d4 * 4);
        w1T[d4 * 4 + 0][e] = v.x;
        w1T[d4 * 4 + 1][e] = v.y;
        w1T[d4 * 4 + 2][e] = v.z;
        w1T[d4 * 4 + 3][e] = v.w;
    }

    int rr = t >> 6, e = t & 63;
#pragma unroll
    for (int rep = 0; rep < 2; rep++) {
        int rb = r0 + rep * 4;
        __syncthreads();
        qrow[rr][e] = g_q[(size_t)(rb + rr) * 64 + e];
        __syncthreads();
        float aq = 0.f;
#pragma unroll 8
        for (int d = 0; d < 64; d++)
            aq = fmaf(qrow[rr][d], w1T[d][e], aq);
        g_qp[(size_t)(rb + rr) * 64 + e] = aq;
    }
}

// =====================================================================
// Main fused kernel — R10/R13 verbatim (best measured): FFMA2 GEMM,
// 512 threads, packed-f32x2 gelu epilogue, radix top-k.
// =====================================================================
#define KS_O    0        // [64][260]
#define VS_O    16640    // [256][72]
#define W3_O    35072    // [64 e][68 f]
#define W1K_O   39424    // [64 e][68 f]
#define A_O     43776    // [2 i][64 e][68 f]
#define QQ_O    52480    // [2][64]
#define QPB_O   52608    // [2][64]
#define SC_O    52736    // [2][256]
#define MAXR_O  53248    // [16]
#define SUMR_O  53264    // [16]
#define PFX_O   53280    // [2] uint
#define NEED_O  53282    // [2] uint
#define HIST_O  53284    // [2][256] uint
#define PART_O  53796    // [2][256]
#define SMEM_FLOATS 54308
#define SMEM_BYTES  (SMEM_FLOATS * 4)   // 217232 B

#define ABS2MASK  0x7fffffff7fffffffULL
#define SIGN2MASK 0x8000000080000000ULL

__global__ __launch_bounds__(512, 1) void main_kernel(
    const float* __restrict__ w1, const float* __restrict__ b1,
    const float* __restrict__ w2, const float* __restrict__ b2)
{
    extern __shared__ float sm[];
    uint32_t* smu = (uint32_t*)sm;
    int t = threadIdx.x, wid = t >> 5, lane = t & 31;
    int bh = blockIdx.y, i0 = blockIdx.x * 4, base = bh * 256;
    int jg = t >> 4;          // 0..31, 8 j each
    int fg = t & 15;          // 0..15, 4 f each

    const ULL C6 = dup2(5.382975e-6f);
    const ULL C5 = dup2(4.88909e-5f);
    const ULL C4 = dup2(3.800358e-5f);
    const ULL C3 = dup2(3.277640e-3f);
    const ULL C2 = dup2(2.1141006e-2f);
    const ULL C1 = dup2(4.986737e-2f);
    const ULL ONE2 = dup2(1.0f);

#pragma unroll
    for (int it = 0; it < 8; it++) {
        int task = t + it * 512;
        int e4 = task & 15, j = task >> 4;
        float4 kv = *(const float4*)(g_k + (size_t)(base + j) * 64 + e4 * 4);
        sm[KS_O + (e4 * 4 + 0) * 260 + j] = kv.x;
        sm[KS_O + (e4 * 4 + 1) * 260 + j] = kv.y;
        sm[KS_O + (e4 * 4 + 2) * 260 + j] = kv.z;
        sm[KS_O + (e4 * 4 + 3) * 260 + j] = kv.w;
        float4 vv = *(const float4*)(g_v + (size_t)(base + j) * 64 + e4 * 4);
        *(float4*)&sm[VS_O + j * 72 + e4 * 4] = vv;
    }
    {
        int f = t >> 3, e0 = (t & 7) * 8;
        float4 a0 = *(const float4*)(w1 + (size_t)f * 192 + 128 + e0);
        float4 a1 = *(const float4*)(w1 + (size_t)f * 192 + 128 + e0 + 4);
        float4 k0 = *(const float4*)(w1 + (size_t)f * 192 + 64 + e0);
        float4 k1 = *(const float4*)(w1 + (size_t)f * 192 + 64 + e0 + 4);
        float av[8] = {a0.x, a0.y, a0.z, a0.w, a1.x, a1.y, a1.z, a1.w};
        float kv[8] = {k0.x, k0.y, k0.z, k0.w, k1.x, k1.y, k1.z, k1.w};
#pragma unroll
        for (int k2 = 0; k2 < 8; k2++) {
            sm[W3_O  + (e0 + k2) * 68 + f] = av[k2];
            sm[W1K_O + (e0 + k2) * 68 + f] = kv[k2];
        }
    }

    ULL W2P0, W2P1;
    {
        float a = __ldg(&w2[fg * 4 + 0]) * 0.5f;
        float b = __ldg(&w2[fg * 4 + 1]) * 0.5f;
        float c = __ldg(&w2[fg * 4 + 2]) * 0.5f;
        float d = __ldg(&w2[fg * 4 + 3]) * 0.5f;
        W2P0 = pack2(a, b);
        W2P1 = pack2(c, d);
    }
    float b2v = __ldg(&b2[0]);

    int fA  = t & 63;
    int iiB = (t >> 6) & 1;
    int e0B = (t >> 7) * 16;

#pragma unroll 1
    for (int p = 0; p < 2; p++) {
        int ia = i0 + p * 2;
        __syncthreads();

        if (t < 128) {
            int ii = t >> 6, f = t & 63;
            sm[QQ_O  + ii * 64 + f] = g_q[(size_t)(base + ia + ii) * 64 + f];
            sm[QPB_O + ii * 64 + f] =
                g_qp[(size_t)(base + ia + ii) * 64 + f] + b1[f];
        }
        __syncthreads();

        {
            const float* qq = sm + QQ_O + iiB * 64;
            float* Adst = sm + A_O + iiB * 4352;
#pragma unroll
            for (int k2 = 0; k2 < 16; k2++) {
                int e = e0B + k2;
                Adst[e * 68 + fA] =
                    fmaf(qq[e], sm[W3_O + e * 68 + fA], sm[W1K_O + e * 68 + fA]);
            }
        }
        __syncthreads();

        ulonglong2 q0 = *(const ulonglong2*)&sm[QPB_O + fg * 4];
        ulonglong2 q1 = *(const ulonglong2*)&sm[QPB_O + 64 + fg * 4];
        ULL acc[2][8][2];
#pragma unroll
        for (int jj = 0; jj < 8; jj++) {
            acc[0][jj][0] = q0.x; acc[0][jj][1] = q0.y;
            acc[1][jj][0] = q1.x; acc[1][jj][1] = q1.y;
        }

#pragma unroll 2
        for (int e = 0; e < 64; e++) {
            float4 k0 = *(const float4*)&sm[KS_O + e * 260 + jg * 8];
            float4 k1 = *(const float4*)&sm[KS_O + e * 260 + jg * 8 + 4];
            ulonglong2 a0 = *(const ulonglong2*)&sm[A_O + e * 68 + fg * 4];
            ulonglong2 a1 = *(const ulonglong2*)&sm[A_O + 4352 + e * 68 + fg * 4];
            float kv[8] = {k0.x, k0.y, k0.z, k0.w, k1.x, k1.y, k1.z, k1.w};
#pragma unroll
            for (int jj = 0; jj < 8; jj++) {
                ULL kd = dup2(kv[jj]);
                fma2(acc[0][jj][0], kd, a0.x);
                fma2(acc[0][jj][1], kd, a0.y);
                fma2(acc[1][jj][0], kd, a1.x);
                fma2(acc[1][jj][1], kd, a1.y);
            }
        }

#pragma unroll
        for (int jj = 0; jj < 8; jj++) {
#pragma unroll
            for (int ii = 0; ii < 2; ii++) {
                ULL S2 = 0ULL;
#pragma unroll
                for (int q = 0; q < 2; q++) {
                    ULL X  = acc[ii][jj][q];
                    ULL AX = X & ABS2MASK;
                    ULL pp = fma2n(C6, AX, C5);
                    pp = fma2n(pp, AX, C4);
                    pp = fma2n(pp, AX, C3);
                    pp = fma2n(pp, AX, C2);
                    pp = fma2n(pp, AX, C1);
                    pp = fma2n(pp, AX, ONE2);
                    float p0, p1;
                    unpack2(pp, p0, p1);
                    float r0f, r1f;
                    asm("rcp.approx.f32 %0, %1;" : "=f"(r0f) : "f"(p0));
                    asm("rcp.approx.f32 %0, %1;" : "=f"(r1f) : "f"(p1));
                    ULL R = pack2(r0f, r1f);
                    ULL R2 = mul2(R, R);
                    ULL R4 = mul2(R2, R2);
                    ULL R8 = mul2(R4, R4);
                    ULL R16 = mul2(R8, R8);
                    ULL T = mul2(AX, R16);
                    ULL G = add2(add2(X, AX), T ^ SIGN2MASK);  // 2*gelu
                    fma2(S2, G, q ? W2P1 : W2P0);
                }
                float slo, shi;
                unpack2(S2, slo, shi);
                float s = slo + shi;
                s += __shfl_xor_sync(0xffffffffu, s, 1);
                s += __shfl_xor_sync(0xffffffffu, s, 2);
                s += __shfl_xor_sync(0xffffffffu, s, 4);
                s += __shfl_xor_sync(0xffffffffu, s, 8);
                if (fg == 0)
                    sm[SC_O + ii * 256 + jg * 8 + jj] = (s + b2v) * 0.125f;
            }
        }
        __syncthreads();

        int ii = t >> 8, j = t & 255;
        float v = sm[SC_O + ii * 256 + j];

        uint32_t u = __float_as_uint(v);
        uint32_t key = (u & 0x80000000u) ? ~u : (u | 0x80000000u);
        if (t < 2) { smu[PFX_O + t] = 0u; smu[NEED_O + t] = 64u; }
#pragma unroll
        for (int r = 0; r < 4; r++) {
            const int shift = 24 - 8 * r;
            smu[HIST_O + t] = 0u;
            __syncthreads();
            uint32_t pfx = smu[PFX_O + ii];
            bool act = (r == 0) || (((key ^ pfx) >> (shift + 8)) == 0u);
            if (act)
                atomicAdd(&smu[HIST_O + ii * 256 + ((key >> shift) & 255u)], 1u);
            __syncthreads();
            if (wid < 2) {
                int nd = (int)smu[NEED_O + wid];
                int bbase = 255 - lane * 8;
                int sct = 0;
#pragma unroll
                for (int k2 = 0; k2 < 8; k2++)
                    sct += (int)smu[HIST_O + wid * 256 + bbase - k2];
                int c = sct;
#pragma unroll
                for (int o = 1; o < 32; o <<= 1) {
                    int x = __shfl_up_sync(0xffffffffu, c, o);
                    if (lane >= o) c += x;
                }
                unsigned mk = __ballot_sync(0xffffffffu, c >= nd);
                int first = __ffs(mk) - 1;
                if (lane == first) {
                    int run = c - sct;
#pragma unroll
                    for (int k2 = 0; k2 < 8; k2++) {
                        int h = (int)smu[HIST_O + wid * 256 + bbase - k2];
                        if (run + h >= nd) {
                            smu[PFX_O + wid] |= ((uint32_t)(bbase - k2)) << shift;
                            smu[NEED_O + wid] = (uint32_t)(nd - run);
                            break;
                        }
                        run += h;
                    }
                }
            }
            __syncthreads();
        }
        uint32_t keyT = smu[PFX_O + ii];
        uint32_t ut = (keyT & 0x80000000u) ? (keyT ^ 0x80000000u) : ~keyT;
        float thr = __uint_as_float(ut);

        float m = v;
#pragma unroll
        for (int o = 16; o; o >>= 1)
            m = fmaxf(m, __shfl_xor_sync(0xffffffffu, m, o));
        if (lane == 0) sm[MAXR_O + wid] = m;
        __syncthreads();
        float mx = sm[MAXR_O + ii * 8];
#pragma unroll
        for (int w = 1; w < 8; w++) mx = fmaxf(mx, sm[MAXR_O + ii * 8 + w]);

        float ev = (v >= thr) ? __expf(v - mx) : 0.f;
        float ssum = ev;
#pragma unroll
        for (int o = 16; o; o >>= 1)
            ssum += __shfl_xor_sync(0xffffffffu, ssum, o);
        if (lane == 0) sm[SUMR_O + wid] = ssum;
        __syncthreads();
        float den = 0.f;
#pragma unroll
        for (int w = 0; w < 8; w++) den += sm[SUMR_O + ii * 8 + w];
        sm[SC_O + ii * 256 + j] = ev / den;
        __syncthreads();

        {
            int g = j >> 6, d = j & 63;
            float a = 0.f;
            const float* ap = sm + SC_O + ii * 256 + g * 64;
            const float* vp = sm + VS_O + g * 64 * 72 + d;
#pragma unroll 8
            for (int jx = 0; jx < 64; jx++)
                a = fmaf(ap[jx], vp[jx * 72], a);
            sm[PART_O + ii * 256 + g * 64 + d] = a;
        }
        __syncthreads();
        if (t < 128) {
            int i2 = t >> 6, dd = t & 63;
            const float* pb = sm + PART_O + i2 * 256;
            float o = pb[dd] + pb[64 + dd] + pb[128 + dd] + pb[192 + dd];
            g_ctx[(size_t)((bh >> 3) * 256 + ia + i2) * 512 + (bh & 7) * 64 + dd] = o;
        }
    }
}

// =====================================================================
extern "C" void kernel_launch(void* const* d_in, const int* in_sizes, int n_in,
                              void* d_out, int out_size)
{
    const float* x  = (const float*)d_in[0];
    const float* Wq = (const float*)d_in[1];
    const float* bq = (const float*)d_in[2];
    const float* Wk = (const float*)d_in[3];
    const float* bk = (const float*)d_in[4];
    const float* Wv = (const float*)d_in[5];
    const float* bv = (const float*)d_in[6];
    const float* w1 = (const float*)d_in[7];
    const float* b1 = (const float*)d_in[8];
    const float* w2 = (const float*)d_in[9];
    const float* b2 = (const float*)d_in[10];
    const float* Wo = (const float*)d_in[11];
    const float* bo = (const float*)d_in[12];
    float* out = (float*)d_out;

    cudaFuncSetAttribute(main_kernel,
                         cudaFuncAttributeMaxDynamicSharedMemorySize, SMEM_BYTES);

    qkv_kernel<<<dim3(8, 16, 3), 128>>>(x, Wq, bq, Wk, bk, Wv, bv);
    qp_kernel<<<512, 256>>>(w1);
    main_kernel<<<dim3(64, 16), 512, SMEM_BYTES>>>(w1, b1, w2, b2);
    outproj_kernel<<<dim3(8, 16), 128>>>(Wo, bo, out);
}

// round 17
// speedup vs baseline: 1.1050x; 1.1050x over previous
#include <cuda_runtime.h>
#include <cuda_bf16.h>
#include <math.h>
#include <stdint.h>

#define Bc   2
#define Cc   256
#define DMc  512
#define Hc   8
#define Dc   64
#define BHc  16
#define ROWS 4096   // B*H*C
#define NQKV (512 * 512)

typedef unsigned long long ULL;

// ---------------- f32x2 packed helpers ----------------
__device__ __forceinline__ void fma2(ULL& d, ULL a, ULL b) {
    asm("fma.rn.f32x2 %0, %1, %2, %0;" : "+l"(d) : "l"(a), "l"(b));
}
__device__ __forceinline__ ULL fma2n(ULL a, ULL b, ULL c) {
    ULL d; asm("fma.rn.f32x2 %0, %1, %2, %3;" : "=l"(d) : "l"(a), "l"(b), "l"(c));
    return d;
}
__device__ __forceinline__ ULL mul2(ULL a, ULL b) {
    ULL d; asm("mul.rn.f32x2 %0, %1, %2;" : "=l"(d) : "l"(a), "l"(b));
    return d;
}
__device__ __forceinline__ ULL add2(ULL a, ULL b) {
    ULL d; asm("add.rn.f32x2 %0, %1, %2;" : "=l"(d) : "l"(a), "l"(b));
    return d;
}
__device__ __forceinline__ ULL dup2(float x) {
    ULL d; asm("mov.b64 %0, {%1, %1};" : "=l"(d) : "f"(x)); return d;
}
__device__ __forceinline__ ULL pack2(float x, float y) {
    ULL d; asm("mov.b64 %0, {%1, %2};" : "=l"(d) : "f"(x), "f"(y)); return d;
}
__device__ __forceinline__ void unpack2(ULL v, float& x, float& y) {
    asm("mov.b64 {%0, %1}, %2;" : "=f"(x), "=f"(y) : "l"(v));
}

// ---------------- device scratch ----------------
__device__ float g_q [ROWS * Dc];
__device__ float g_k [ROWS * Dc];
__device__ float g_v [ROWS * Dc];
__device__ float g_qp[ROWS * Dc];
__device__ float g_ctx[Bc * Cc * DMc];
__device__ float g_pout[4][NQKV];   // outproj split-K partials ([m][e])

// =====================================================================
// Full-K projection GEMM (R13 verbatim — q/k numerics are PINNED:
// single sequential fp32 chain over k=0..511 per output element).
// 64x64 tile @ 512 threads, double-buffered smem, bias in epilogue.
// =====================================================================
__device__ __forceinline__ void gemm512_big(
    const float* __restrict__ A, const float* __restrict__ W,
    const float* __restrict__ bias, float* __restrict__ out, bool scatter,
    int m0, int n0)
{
    __shared__ float Xs[2][16][68];
    __shared__ float Wsh[2][16][68];
    int t  = threadIdx.x;
    int tx = t & 15, ty = t >> 4;        // ty 0..31
    int half = t >> 8;                   // 0: X loader, 1: W loader
    int lr = (t & 255) >> 2;             // row 0..63
    int kq = (t & 3) * 4;
    const float* src = half ? W : A;
    int rbase = half ? n0 : m0;
    const float* rowp = src + (size_t)(rbase + lr) * 512;

    ULL acc[2][2];
    acc[0][0] = 0ULL; acc[0][1] = 0ULL;
    acc[1][0] = 0ULL; acc[1][1] = 0ULL;

    {
        float4 v = *(const float4*)(rowp + kq);
        float* dst = half ? &Wsh[0][0][0] : &Xs[0][0][0];
        dst[(kq + 0) * 68 + lr] = v.x;
        dst[(kq + 1) * 68 + lr] = v.y;
        dst[(kq + 2) * 68 + lr] = v.z;
        dst[(kq + 3) * 68 + lr] = v.w;
    }
    __syncthreads();

    for (int kc = 0; kc < 512; kc += 16) {
        int cur = (kc >> 4) & 1;
        float4 v;
        bool more = (kc + 16 < 512);
        if (more) v = *(const float4*)(rowp + kc + 16 + kq);

        const float (*Xc)[68] = Xs[cur];
        const float (*Wc)[68] = Wsh[cur];
#pragma unroll
        for (int kk = 0; kk < 16; kk++) {
            ulonglong2 wb = *(const ulonglong2*)&Wc[kk][tx * 4];
            ULL a0 = dup2(Xc[kk][ty * 2 + 0]);
            ULL a1 = dup2(Xc[kk][ty * 2 + 1]);
            fma2(acc[0][0], a0, wb.x);
            fma2(acc[0][1], a0, wb.y);
            fma2(acc[1][0], a1, wb.x);
            fma2(acc[1][1], a1, wb.y);
        }
        if (more) {
            float* dst = half ? &Wsh[cur ^ 1][0][0] : &Xs[cur ^ 1][0][0];
            dst[(kq + 0) * 68 + lr] = v.x;
            dst[(kq + 1) * 68 + lr] = v.y;
            dst[(kq + 2) * 68 + lr] = v.z;
            dst[(kq + 3) * 68 + lr] = v.w;
            __syncthreads();
        }
    }

    int nb = n0 + tx * 4;
    float bb0 = bias[nb + 0], bb1 = bias[nb + 1];
    float bb2 = bias[nb + 2], bb3 = bias[nb + 3];
#pragma unroll
    for (int mm = 0; mm < 2; mm++) {
        int m = m0 + ty * 2 + mm;
        float f0, f1, f2, f3;
        unpack2(acc[mm][0], f0, f1);
        unpack2(acc[mm][1], f2, f3);
        f0 += bb0; f1 += bb1; f2 += bb2; f3 += bb3;
        if (scatter) {
            int b = m >> 8, c = m & 255;
            int h = nb >> 6, d0 = nb & 63;
            *(float4*)(out + ((size_t)((b * 8 + h) * 256 + c)) * 64 + d0) =
                make_float4(f0, f1, f2, f3);
        } else {
            *(float4*)(out + (size_t)m * 512 + nb) = make_float4(f0, f1, f2, f3);
        }
    }
}

__global__ __launch_bounds__(512) void qkv_kernel(
    const float* __restrict__ x,
    const float* __restrict__ Wq, const float* __restrict__ bq,
    const float* __restrict__ Wk, const float* __restrict__ bk,
    const float* __restrict__ Wv, const float* __restrict__ bv)
{
    int z = blockIdx.z;
    const float* W = (z == 0) ? Wq : (z == 1) ? Wk : Wv;
    const float* b = (z == 0) ? bq : (z == 1) ? bk : bv;
    float* out     = (z == 0) ? g_q : (z == 1) ? g_k : g_v;
    gemm512_big(x, W, b, out, true, blockIdx.y * 64, blockIdx.x * 64);
}

// =====================================================================
// Outproj split-K (SAFE: no top-k downstream of `out`): 64x64 tile @
// 512 threads, K slice of 128 per z, partial buffers + fixed-order reduce.
// =====================================================================
__global__ __launch_bounds__(512) void outproj_kernel(const float* __restrict__ Wo)
{
    __shared__ float Xs[2][16][68];
    __shared__ float Wsh[2][16][68];
    int m0 = blockIdx.y * 64, n0 = blockIdx.x * 64;
    int k0 = blockIdx.z * 128;
    float* out = g_pout[blockIdx.z];

    int t  = threadIdx.x;
    int tx = t & 15, ty = t >> 4;
    int half = t >> 8;
    int lr = (t & 255) >> 2;
    int kq = (t & 3) * 4;
    const float* src = half ? Wo : g_ctx;
    int rbase = half ? n0 : m0;
    const float* rowp = src + (size_t)(rbase + lr) * 512 + k0;

    ULL acc[2][2];
    acc[0][0] = 0ULL; acc[0][1] = 0ULL;
    acc[1][0] = 0ULL; acc[1][1] = 0ULL;

    {
        float4 v = *(const float4*)(rowp + kq);
        float* dst = half ? &Wsh[0][0][0] : &Xs[0][0][0];
        dst[(kq + 0) * 68 + lr] = v.x;
        dst[(kq + 1) * 68 + lr] = v.y;
        dst[(kq + 2) * 68 + lr] = v.z;
        dst[(kq + 3) * 68 + lr] = v.w;
    }
    __syncthreads();

    for (int kc = 0; kc < 128; kc += 16) {
        int cur = (kc >> 4) & 1;
        float4 v;
        bool more = (kc + 16 < 128);
        if (more) v = *(const float4*)(rowp + kc + 16 + kq);

        const float (*Xc)[68] = Xs[cur];
        const float (*Wc)[68] = Wsh[cur];
#pragma unroll
        for (int kk = 0; kk < 16; kk++) {
            ulonglong2 wb = *(const ulonglong2*)&Wc[kk][tx * 4];
            ULL a0 = dup2(Xc[kk][ty * 2 + 0]);
            ULL a1 = dup2(Xc[kk][ty * 2 + 1]);
            fma2(acc[0][0], a0, wb.x);
            fma2(acc[0][1], a0, wb.y);
            fma2(acc[1][0], a1, wb.x);
            fma2(acc[1][1], a1, wb.y);
        }
        if (more) {
            float* dst = half ? &Wsh[cur ^ 1][0][0] : &Xs[cur ^ 1][0][0];
            dst[(kq + 0) * 68 + lr] = v.x;
            dst[(kq + 1) * 68 + lr] = v.y;
            dst[(kq + 2) * 68 + lr] = v.z;
            dst[(kq + 3) * 68 + lr] = v.w;
            __syncthreads();
        }
    }

    int nb = n0 + tx * 4;
#pragma unroll
    for (int mm = 0; mm < 2; mm++) {
        int m = m0 + ty * 2 + mm;
        float f0, f1, f2, f3;
        unpack2(acc[mm][0], f0, f1);
        unpack2(acc[mm][1], f2, f3);
        *(float4*)(out + (size_t)m * 512 + nb) = make_float4(f0, f1, f2, f3);
    }
}

__global__ __launch_bounds__(512) void add_out_kernel(
    const float* __restrict__ bo, float* __restrict__ out)
{
    int i = (blockIdx.x * 512 + threadIdx.x) * 4;
    float4 p0 = *(const float4*)(g_pout[0] + i);
    float4 p1 = *(const float4*)(g_pout[1] + i);
    float4 p2 = *(const float4*)(g_pout[2] + i);
    float4 p3 = *(const float4*)(g_pout[3] + i);
    float4 bv = *(const float4*)(bo + (i & 511));
    *(float4*)(out + i) = make_float4(
        ((p0.x + p1.x) + (p2.x + p3.x)) + bv.x,
        ((p0.y + p1.y) + (p2.y + p3.y)) + bv.y,
        ((p0.z + p1.z) + (p2.z + p3.z)) + bv.z,
        ((p0.w + p1.w) + (p2.w + p3.w)) + bv.w);
}

// =====================================================================
// q_p:  g_qp[r][e] = sum_d g_q[r][d] * w1[e][d]
// =====================================================================
__global__ __launch_bounds__(256) void qp_kernel(const float* __restrict__ w1)
{
    __shared__ float w1T[64][68];
    __shared__ float qrow[4][64];
    int t = threadIdx.x;
    int r0 = blockIdx.x * 8;

#pragma unroll
    for (int it = 0; it < 4; it++) {
        int task = t + it * 256;
        int d4 = task & 15;
        int e  = (task >> 4) & 63;
        float4 v = *(const float4*)(w1 + (size_t)e * 192 + d4 * 4);
        w1T[d4 * 4 + 0][e] = v.x;
        w1T[d4 * 4 + 1][e] = v.y;
        w1T[d4 * 4 + 2][e] = v.z;
        w1T[d4 * 4 + 3][e] = v.w;
    }

    int rr = t >> 6, e = t & 63;
#pragma unroll
    for (int rep = 0; rep < 2; rep++) {
        int rb = r0 + rep * 4;
        __syncthreads();
        qrow[rr][e] = g_q[(size_t)(rb + rr) * 64 + e];
        __syncthreads();
        float aq = 0.f;
#pragma unroll 8
        for (int d = 0; d < 64; d++)
            aq = fmaf(qrow[rr][d], w1T[d][e], aq);
        g_qp[(size_t)(rb + rr) * 64 + e] = aq;
    }
}

// =====================================================================
// Main fused kernel — R13 verbatim (best measured): FFMA2 GEMM,
// 512 threads, packed-f32x2 gelu epilogue, radix top-k.
// =====================================================================
#define KS_O    0        // [64][260]
#define VS_O    16640    // [256][72]
#define W3_O    35072    // [64 e][68 f]
#define W1K_O   39424    // [64 e][68 f]
#define A_O     43776    // [2 i][64 e][68 f]
#define QQ_O    52480    // [2][64]
#define QPB_O   52608    // [2][64]
#define SC_O    52736    // [2][256]
#define MAXR_O  53248    // [16]
#define SUMR_O  53264    // [16]
#define PFX_O   53280    // [2] uint
#define NEED_O  53282    // [2] uint
#define HIST_O  53284    // [2][256] uint
#define PART_O  53796    // [2][256]
#define SMEM_FLOATS 54308
#define SMEM_BYTES  (SMEM_FLOATS * 4)   // 217232 B

#define ABS2MASK  0x7fffffff7fffffffULL
#define SIGN2MASK 0x8000000080000000ULL

__global__ __launch_bounds__(512, 1) void main_kernel(
    const float* __restrict__ w1, const float* __restrict__ b1,
    const float* __restrict__ w2, const float* __restrict__ b2)
{
    extern __shared__ float sm[];
    uint32_t* smu = (uint32_t*)sm;
    int t = threadIdx.x, wid = t >> 5, lane = t & 31;
    int bh = blockIdx.y, i0 = blockIdx.x * 4, base = bh * 256;
    int jg = t >> 4;          // 0..31, 8 j each
    int fg = t & 15;          // 0..15, 4 f each

    const ULL C6 = dup2(5.382975e-6f);
    const ULL C5 = dup2(4.88909e-5f);
    const ULL C4 = dup2(3.800358e-5f);
    const ULL C3 = dup2(3.277640e-3f);
    const ULL C2 = dup2(2.1141006e-2f);
    const ULL C1 = dup2(4.986737e-2f);
    const ULL ONE2 = dup2(1.0f);

#pragma unroll
    for (int it = 0; it < 8; it++) {
        int task = t + it * 512;
        int e4 = task & 15, j = task >> 4;
        float4 kv = *(const float4*)(g_k + (size_t)(base + j) * 64 + e4 * 4);
        sm[KS_O + (e4 * 4 + 0) * 260 + j] = kv.x;
        sm[KS_O + (e4 * 4 + 1) * 260 + j] = kv.y;
        sm[KS_O + (e4 * 4 + 2) * 260 + j] = kv.z;
        sm[KS_O + (e4 * 4 + 3) * 260 + j] = kv.w;
        float4 vv = *(const float4*)(g_v + (size_t)(base + j) * 64 + e4 * 4);
        *(float4*)&sm[VS_O + j * 72 + e4 * 4] = vv;
    }
    {
        int f = t >> 3, e0 = (t & 7) * 8;
        float4 a0 = *(const float4*)(w1 + (size_t)f * 192 + 128 + e0);
        float4 a1 = *(const float4*)(w1 + (size_t)f * 192 + 128 + e0 + 4);
        float4 k0 = *(const float4*)(w1 + (size_t)f * 192 + 64 + e0);
        float4 k1 = *(const float4*)(w1 + (size_t)f * 192 + 64 + e0 + 4);
        float av[8] = {a0.x, a0.y, a0.z, a0.w, a1.x, a1.y, a1.z, a1.w};
        float kv[8] = {k0.x, k0.y, k0.z, k0.w, k1.x, k1.y, k1.z, k1.w};
#pragma unroll
        for (int k2 = 0; k2 < 8; k2++) {
            sm[W3_O  + (e0 + k2) * 68 + f] = av[k2];
            sm[W1K_O + (e0 + k2) * 68 + f] = kv[k2];
        }
    }

    ULL W2P0, W2P1;
    {
        float a = __ldg(&w2[fg * 4 + 0]) * 0.5f;
        float b = __ldg(&w2[fg * 4 + 1]) * 0.5f;
        float c = __ldg(&w2[fg * 4 + 2]) * 0.5f;
        float d = __ldg(&w2[fg * 4 + 3]) * 0.5f;
        W2P0 = pack2(a, b);
        W2P1 = pack2(c, d);
    }
    float b2v = __ldg(&b2[0]);

    int fA  = t & 63;
    int iiB = (t >> 6) & 1;
    int e0B = (t >> 7) * 16;

#pragma unroll 1
    for (int p = 0; p < 2; p++) {
        int ia = i0 + p * 2;
        __syncthreads();

        if (t < 128) {
            int ii = t >> 6, f = t & 63;
            sm[QQ_O  + ii * 64 + f] = g_q[(size_t)(base + ia + ii) * 64 + f];
            sm[QPB_O + ii * 64 + f] =
                g_qp[(size_t)(base + ia + ii) * 64 + f] + b1[f];
        }
        __syncthreads();

        {
            const float* qq = sm + QQ_O + iiB * 64;
            float* Adst = sm + A_O + iiB * 4352;
#pragma unroll
            for (int k2 = 0; k2 < 16; k2++) {
                int e = e0B + k2;
                Adst[e * 68 + fA] =
                    fmaf(qq[e], sm[W3_O + e * 68 + fA], sm[W1K_O + e * 68 + fA]);
            }
        }
        __syncthreads();

        ulonglong2 q0 = *(const ulonglong2*)&sm[QPB_O + fg * 4];
        ulonglong2 q1 = *(const ulonglong2*)&sm[QPB_O + 64 + fg * 4];
        ULL acc[2][8][2];
#pragma unroll
        for (int jj = 0; jj < 8; jj++) {
            acc[0][jj][0] = q0.x; acc[0][jj][1] = q0.y;
            acc[1][jj][0] = q1.x; acc[1][jj][1] = q1.y;
        }

#pragma unroll 2
        for (int e = 0; e < 64; e++) {
            float4 k0 = *(const float4*)&sm[KS_O + e * 260 + jg * 8];
            float4 k1 = *(const float4*)&sm[KS_O + e * 260 + jg * 8 + 4];
            ulonglong2 a0 = *(const ulonglong2*)&sm[A_O + e * 68 + fg * 4];
            ulonglong2 a1 = *(const ulonglong2*)&sm[A_O + 4352 + e * 68 + fg * 4];
            float kv[8] = {k0.x, k0.y, k0.z, k0.w, k1.x, k1.y, k1.z, k1.w};
#pragma unroll
            for (int jj = 0; jj < 8; jj++) {
                ULL kd = dup2(kv[jj]);
                fma2(acc[0][jj][0], kd, a0.x);
                fma2(acc[0][jj][1], kd, a0.y);
                fma2(acc[1][jj][0], kd, a1.x);
                fma2(acc[1][jj][1], kd, a1.y);
            }
        }

#pragma unroll
        for (int jj = 0; jj < 8; jj++) {
#pragma unroll
            for (int ii = 0; ii < 2; ii++) {
                ULL S2 = 0ULL;
#pragma unroll
                for (int q = 0; q < 2; q++) {
                    ULL X  = acc[ii][jj][q];
                    ULL AX = X & ABS2MASK;
                    ULL pp = fma2n(C6, AX, C5);
                    pp = fma2n(pp, AX, C4);
                    pp = fma2n(pp, AX, C3);
                    pp = fma2n(pp, AX, C2);
                    pp = fma2n(pp, AX, C1);
                    pp = fma2n(pp, AX, ONE2);
                    float p0, p1;
                    unpack2(pp, p0, p1);
                    float r0f, r1f;
                    asm("rcp.approx.f32 %0, %1;" : "=f"(r0f) : "f"(p0));
                    asm("rcp.approx.f32 %0, %1;" : "=f"(r1f) : "f"(p1));
                    ULL R = pack2(r0f, r1f);
                    ULL R2 = mul2(R, R);
                    ULL R4 = mul2(R2, R2);
                    ULL R8 = mul2(R4, R4);
                    ULL R16 = mul2(R8, R8);
                    ULL T = mul2(AX, R16);
                    ULL G = add2(add2(X, AX), T ^ SIGN2MASK);  // 2*gelu
                    fma2(S2, G, q ? W2P1 : W2P0);
                }
                float slo, shi;
                unpack2(S2, slo, shi);
                float s = slo + shi;
                s += __shfl_xor_sync(0xffffffffu, s, 1);
                s += __shfl_xor_sync(0xffffffffu, s, 2);
                s += __shfl_xor_sync(0xffffffffu, s, 4);
                s += __shfl_xor_sync(0xffffffffu, s, 8);
                if (fg == 0)
                    sm[SC_O + ii * 256 + jg * 8 + jj] = (s + b2v) * 0.125f;
            }
        }
        __syncthreads();

        int ii = t >> 8, j = t & 255;
        float v = sm[SC_O + ii * 256 + j];

        uint32_t u = __float_as_uint(v);
        uint32_t key = (u & 0x80000000u) ? ~u : (u | 0x80000000u);
        if (t < 2) { smu[PFX_O + t] = 0u; smu[NEED_O + t] = 64u; }
#pragma unroll
        for (int r = 0; r < 4; r++) {
            const int shift = 24 - 8 * r;
            smu[HIST_O + t] = 0u;
            __syncthreads();
            uint32_t pfx = smu[PFX_O + ii];
            bool act = (r == 0) || (((key ^ pfx) >> (shift + 8)) == 0u);
            if (act)
                atomicAdd(&smu[HIST_O + ii * 256 + ((key >> shift) & 255u)], 1u);
            __syncthreads();
            if (wid < 2) {
                int nd = (int)smu[NEED_O + wid];
                int bbase = 255 - lane * 8;
                int sct = 0;
#pragma unroll
                for (int k2 = 0; k2 < 8; k2++)
                    sct += (int)smu[HIST_O + wid * 256 + bbase - k2];
                int c = sct;
#pragma unroll
                for (int o = 1; o < 32; o <<= 1) {
                    int x = __shfl_up_sync(0xffffffffu, c, o);
                    if (lane >= o) c += x;
                }
                unsigned mk = __ballot_sync(0xffffffffu, c >= nd);
                int first = __ffs(mk) - 1;
                if (lane == first) {
                    int run = c - sct;
#pragma unroll
                    for (int k2 = 0; k2 < 8; k2++) {
                        int h = (int)smu[HIST_O + wid * 256 + bbase - k2];
                        if (run + h >= nd) {
                            smu[PFX_O + wid] |= ((uint32_t)(bbase - k2)) << shift;
                            smu[NEED_O + wid] = (uint32_t)(nd - run);
                            break;
                        }
                        run += h;
                    }
                }
            }
            __syncthreads();
        }
        uint32_t keyT = smu[PFX_O + ii];
        uint32_t ut = (keyT & 0x80000000u) ? (keyT ^ 0x80000000u) : ~keyT;
        float thr = __uint_as_float(ut);

        float m = v;
#pragma unroll
        for (int o = 16; o; o >>= 1)
            m = fmaxf(m, __shfl_xor_sync(0xffffffffu, m, o));
        if (lane == 0) sm[MAXR_O + wid] = m;
        __syncthreads();
        float mx = sm[MAXR_O + ii * 8];
#pragma unroll
        for (int w = 1; w < 8; w++) mx = fmaxf(mx, sm[MAXR_O + ii * 8 + w]);

        float ev = (v >= thr) ? __expf(v - mx) : 0.f;
        float ssum = ev;
#pragma unroll
        for (int o = 16; o; o >>= 1)
            ssum += __shfl_xor_sync(0xffffffffu, ssum, o);
        if (lane == 0) sm[SUMR_O + wid] = ssum;
        __syncthreads();
        float den = 0.f;
#pragma unroll
        for (int w = 0; w < 8; w++) den += sm[SUMR_O + ii * 8 + w];
        sm[SC_O + ii * 256 + j] = ev / den;
        __syncthreads();

        {
            int g = j >> 6, d = j & 63;
            float a = 0.f;
            const float* ap = sm + SC_O + ii * 256 + g * 64;
            const float* vp = sm + VS_O + g * 64 * 72 + d;
#pragma unroll 8
            for (int jx = 0; jx < 64; jx++)
                a = fmaf(ap[jx], vp[jx * 72], a);
            sm[PART_O + ii * 256 + g * 64 + d] = a;
        }
        __syncthreads();
        if (t < 128) {
            int i2 = t >> 6, dd = t & 63;
            const float* pb = sm + PART_O + i2 * 256;
            float o = pb[dd] + pb[64 + dd] + pb[128 + dd] + pb[192 + dd];
            g_ctx[(size_t)((bh >> 3) * 256 + ia + i2) * 512 + (bh & 7) * 64 + dd] = o;
        }
    }
}

// =====================================================================
extern "C" void kernel_launch(void* const* d_in, const int* in_sizes, int n_in,
                              void* d_out, int out_size)
{
    const float* x  = (const float*)d_in[0];
    const float* Wq = (const float*)d_in[1];
    const float* bq = (const float*)d_in[2];
    const float* Wk = (const float*)d_in[3];
    const float* bk = (const float*)d_in[4];
    const float* Wv = (const float*)d_in[5];
    const float* bv = (const float*)d_in[6];
    const float* w1 = (const float*)d_in[7];
    const float* b1 = (const float*)d_in[8];
    const float* w2 = (const float*)d_in[9];
    const float* b2 = (const float*)d_in[10];
    const float* Wo = (const float*)d_in[11];
    const float* bo = (const float*)d_in[12];
    float* out = (float*)d_out;

    cudaFuncSetAttribute(main_kernel,
                         cudaFuncAttributeMaxDynamicSharedMemorySize, SMEM_BYTES);

    qkv_kernel<<<dim3(8, 8, 3), 512>>>(x, Wq, bq, Wk, bk, Wv, bv);
    qp_kernel<<<512, 256>>>(w1);
    main_kernel<<<dim3(64, 16), 512, SMEM_BYTES>>>(w1, b1, w2, b2);
    outproj_kernel<<<dim3(8, 8, 4), 512>>>(Wo);
    add_out_kernel<<<128, 512>>>(bo, out);
}